// round 12
// baseline (speedup 1.0000x reference)
#include <cuda_runtime.h>
#include <cuda_fp16.h>
#include <math.h>
#include <stdint.h>

// ---------------- problem constants (fixed by dataset) ----------------
#define B_     8
#define T2_    27
#define T3_    9
#define P_     17
#define C_     128
#define BT2_   216
#define LQ_    153
#define LV_    4080
#define NH_    8
#define NL_    4
#define NP_    4
#define DH_    16
#define NROWS_ (BT2_*LQ_)     // 33048
#define MVAL_  (BT2_*LV_)     // 881280
#define NEWQ_SIZE_ ((size_t)NROWS_*C_)
#define NOFF_  256
#define NCAT_  384

// ---------------- scratch ----------------
__device__ float g_offatt[(size_t)NROWS_ * NCAT_];
__device__ float g_samp[(size_t)NROWS_ * C_];
__device__ float g_bcat[NCAT_];
// fp16 weight images, XOR-swizzled [n][k] layout, 5 chunks of 128x128:
// 0: W_val, 1: W_off[0:128), 2: W_off[128:256), 3: W_attn, 4: W_out
__device__ uint32_t g_wb[5 * 8192];   // 32KB per chunk

__device__ __forceinline__ uint32_t smem_u32(const void* p) {
    uint32_t a;
    asm("{ .reg .u64 t; cvta.to.shared.u64 t, %1; cvt.u32.u64 %0, t; }" : "=r"(a) : "l"(p));
    return a;
}

// swizzled byte offset within a 256B row (B images only)
__device__ __forceinline__ uint32_t swz(uint32_t c, uint32_t rm) {
    return (c & 15u) | ((((c >> 4) ^ rm) & 15u) << 4);
}

// ---------------- prep: build 5 fp16 weight-chunk images ----------------
__global__ void prep_images(const float* __restrict__ W_val,
                            const float* __restrict__ W_off,
                            const float* __restrict__ W_attn,
                            const float* __restrict__ W_out)
{
    const float* srcs[5] = {W_val, W_off, W_off + 16384, W_attn, W_out};
    const float* W = srcs[blockIdx.x];
    unsigned short* img = (unsigned short*)(g_wb + blockIdx.x * 8192);
    for (int i = threadIdx.x; i < 16384; i += 256) {
        int n = i >> 7, k = i & 127;
        __half h = __float2half_rn(W[i]);
        uint32_t byte = (uint32_t)n * 256u + swz((uint32_t)k * 2u, (uint32_t)(n & 7));
        img[byte >> 1] = *(unsigned short*)&h;
    }
}

__global__ void concat_bias(const float* __restrict__ boff, const float* __restrict__ battn) {
    int i = threadIdx.x;
    if (i < NCAT_) g_bcat[i] = (i < NOFF_) ? boff[i] : battn[i - NOFF_];
}

// ---------------- ldmatrix / mma helpers ----------------
#define LDSM4(r0, r1, r2, r3, addr) \
    asm volatile("ldmatrix.sync.aligned.m8n8.x4.shared.b16 {%0,%1,%2,%3}, [%4];" \
                 : "=r"(r0), "=r"(r1), "=r"(r2), "=r"(r3) : "r"(addr))

#define MMAH16816(c, a, b0, b1) \
    asm volatile("mma.sync.aligned.m16n8k16.row.col.f32.f16.f16.f32 " \
                 "{%0,%1,%2,%3},{%4,%5,%6,%7},{%8,%9},{%0,%1,%2,%3};" \
                 : "+f"((c)[0]), "+f"((c)[1]), "+f"((c)[2]), "+f"((c)[3]) \
                 : "r"((a)[0]), "r"((a)[1]), "r"((a)[2]), "r"((a)[3]), "r"(b0), "r"(b1))

// float2 -> fp16x2 hi + exact fp16x2 residual (a = h + l to ~22 bits)
__device__ __forceinline__ void split2h(float2 v, uint32_t& h, uint32_t& l) {
    __half2 hh = __floats2half2_rn(v.x, v.y);
    float2 hf = __half22float2(hh);
    __half2 ll = __floats2half2_rn(v.x - hf.x, v.y - hf.y);
    h = *(uint32_t*)&hh;
    l = *(uint32_t*)&ll;
}

// ---------------- unified HMMA fp16 2-term-split GEMM ----------------
// Out = A * W^T + bias.  A split to fp16 hi+lo (exact to ~22 bits),
// W rounded to fp16 (only precision loss, ~1.4e-4 rel).
// CTA: 128 threads (4 warps), tile 64(M) x 128(N), K = 128, warp 32x64.
// A staged in smem fp16 hi/lo images with PADDED rows (272B stride):
// coalesced LDG.128 -> in-reg split -> conflict-free STS.128 -> LDSM (no XOR).
// B image (32KB, XOR-swizzled) copied once. smem ~66KB -> 3 CTAs/SM.
#define CTM 64
#define AROWB 272                      // 256B data + 16B pad
#define AHI_OFF 0
#define ALO_OFF (64 * AROWB)           // 17408
#define BIM_OFF (2 * 64 * AROWB)       // 34816
#define VP_SMEM (BIM_OFF + 32768)      // 67584

__global__ __launch_bounds__(128, 3)
void hmma_gemm(const float* __restrict__ A,
               const uint32_t* __restrict__ wimg_base,
               const float* __restrict__ bias_base,
               float* __restrict__ Out,
               int M, int ldout, int mtiles)
{
    extern __shared__ char sm[];
    const uint32_t sbase = smem_u32(sm);
    const int tid = threadIdx.x;
    const int wid = tid >> 5;
    const int lane = tid & 31;
    const int wm = wid & 1;          // m half (32 rows)
    const int wn = wid >> 1;         // n half (64 cols)
    const int colbase = blockIdx.y * 128;
    const float* bias = bias_base + colbase;

    // copy this chunk's pre-swizzled fp16 W image into smem (once)
    {
        const float4* s4 = (const float4*)(wimg_base + blockIdx.y * 8192);
        float4* d4 = (float4*)(sm + BIM_OFF);
#pragma unroll
        for (int i = 0; i < 16; i++) d4[tid + i * 128] = s4[tid + i * 128];
    }

    // A fragment LDSM addressing (padded-linear, loop-invariant)
    const int sel = lane >> 3;            // 0..3
    const int li  = lane & 7;
    const int achunkbit = sel >> 1;       // k-half of the 32B (2-chunk) k-step
    uint32_t aHiB[2], aLoB[2];
#pragma unroll
    for (int s = 0; s < 2; s++) {
        int arow = wm * 32 + s * 16 + li + (sel & 1) * 8;
        aHiB[s] = sbase + AHI_OFF + (uint32_t)arow * AROWB;
        aLoB[s] = sbase + ALO_OFF + (uint32_t)arow * AROWB;
    }
    // B fragment addressing (XOR-swizzled image, as before)
    const int bchunkbit = sel & 1;
    const int bro = (sel >> 1) * 8 + li;
    uint32_t bBase[4];
#pragma unroll
    for (int g = 0; g < 4; g++) {
        uint32_t nrow = (uint32_t)(wn * 64 + g * 16 + bro);
        bBase[g] = sbase + BIM_OFF + nrow * 256u;
    }

    // conversion addressing: warp w handles rows [16w,16w+16), 4 rows per phase
    const int crw = lane >> 3;            // row within 4-row group
    const int cf0 = 2 * (lane & 7);       // float4 index base (0,2,..,14)

    for (int tile = blockIdx.x; tile < mtiles; tile += gridDim.x) {
        const int bm = tile * CTM;
        __syncthreads();   // prior LDSM readers done; W copy done (iter 0)

        // stage this tile's 64x128 A rows as fp16 hi/lo padded images
#pragma unroll
        for (int rg = 0; rg < 4; rg++) {
            const int row = wid * 16 + rg * 4 + crw;
            const int grow = bm + row;
            const bool valid = grow < M;
            const float4* src = (const float4*)(A + (size_t)grow * 128);
            uint32_t hrow = sbase + AHI_OFF + (uint32_t)row * AROWB;
            uint32_t lrow = sbase + ALO_OFF + (uint32_t)row * AROWB;
#pragma unroll
            for (int it = 0; it < 2; it++) {
                const int f = cf0 + 16 * it;        // float4 index 0..31
                float4 v0 = valid ? src[f]     : make_float4(0.f, 0.f, 0.f, 0.f);
                float4 v1 = valid ? src[f + 1] : make_float4(0.f, 0.f, 0.f, 0.f);
                uint32_t h0, h1, h2, h3, l0, l1, l2, l3;
                split2h(make_float2(v0.x, v0.y), h0, l0);
                split2h(make_float2(v0.z, v0.w), h1, l1);
                split2h(make_float2(v1.x, v1.y), h2, l2);
                split2h(make_float2(v1.z, v1.w), h3, l3);
                const uint32_t qoff = (uint32_t)(f / 2) * 16u;   // 16B chunk offset
                asm volatile("st.shared.v4.b32 [%0], {%1,%2,%3,%4};"
                             :: "r"(hrow + qoff), "r"(h0), "r"(h1), "r"(h2), "r"(h3));
                asm volatile("st.shared.v4.b32 [%0], {%1,%2,%3,%4};"
                             :: "r"(lrow + qoff), "r"(l0), "r"(l1), "r"(l2), "r"(l3));
            }
        }
        __syncthreads();

        float c[2][8][4];
#pragma unroll
        for (int s = 0; s < 2; s++)
#pragma unroll
            for (int t = 0; t < 8; t++)
#pragma unroll
                for (int j = 0; j < 4; j++) c[s][t][j] = 0.f;

#pragma unroll
        for (int kk = 0; kk < 8; kk++) {
            const uint32_t offA = (uint32_t)((kk * 2 + achunkbit) << 4);   // linear
            const uint32_t offB = (uint32_t)(((kk * 2 + bchunkbit) ^ li) << 4);

            uint32_t ah[2][4], al[2][4];
#pragma unroll
            for (int s = 0; s < 2; s++) {
                LDSM4(ah[s][0], ah[s][1], ah[s][2], ah[s][3], aHiB[s] + offA);
                LDSM4(al[s][0], al[s][1], al[s][2], al[s][3], aLoB[s] + offA);
            }

#pragma unroll
            for (int g = 0; g < 4; g++) {
                uint32_t bh[4];
                LDSM4(bh[0], bh[1], bh[2], bh[3], bBase[g] + offB);
#pragma unroll
                for (int s = 0; s < 2; s++) {
                    MMAH16816(c[s][2 * g],     ah[s], bh[0], bh[1]);
                    MMAH16816(c[s][2 * g + 1], ah[s], bh[2], bh[3]);
                }
#pragma unroll
                for (int s = 0; s < 2; s++) {
                    MMAH16816(c[s][2 * g],     al[s], bh[0], bh[1]);
                    MMAH16816(c[s][2 * g + 1], al[s], bh[2], bh[3]);
                }
            }
        }

        // epilogue: bias + direct global stores
        {
            const int ncol = wn * 64 + 2 * (lane & 3);
#pragma unroll
            for (int s = 0; s < 2; s++) {
                const int m0 = bm + wm * 32 + s * 16 + (lane >> 2);
                const bool v0 = m0 < M;
                const bool v1 = (m0 + 8) < M;
                float* o0 = Out + (size_t)m0 * ldout + colbase;
                float* o1 = Out + (size_t)(m0 + 8) * ldout + colbase;
#pragma unroll
                for (int t = 0; t < 8; t++) {
                    int n = ncol + t * 8;
                    float2 bb = __ldg((const float2*)(bias + n));
                    if (v0) *(float2*)(o0 + n) = make_float2(c[s][t][0] + bb.x, c[s][t][1] + bb.y);
                    if (v1) *(float2*)(o1 + n) = make_float2(c[s][t][2] + bb.x, c[s][t][3] + bb.y);
                }
            }
        }
    }
}

// ---------------- deformable bilinear gather (softmax fused) ----------------
__global__ __launch_bounds__(128) void gather_kernel(
    const float* __restrict__ newv,
    const float* __restrict__ refp)
{
    int g = blockIdx.x * 4 + (threadIdx.x >> 5);
    int r = g >> 3;
    int h = g & 7;
    int lane = threadIdx.x & 31;
    int s = lane >> 1;           // sample 0..15
    int half = lane & 1;
    int l = s >> 2, p = s & 3;
    int b = r / LQ_;

    const int W = 48 >> l;
    const int H = 64 >> l;
    const int start = 4096 - (4096 >> (2 * l));

    int sidx = (h * 4 + l) * 4 + p;
    const float* orow = g_offatt + (size_t)r * NCAT_;
    float offx = orow[sidx * 2 + 0];
    float offy = orow[sidx * 2 + 1];

    // fused softmax over the 16 samples of this (r,h)
    float logit = orow[NOFF_ + h * 16 + s];
    float mx = logit;
#pragma unroll
    for (int m = 2; m <= 16; m <<= 1) mx = fmaxf(mx, __shfl_xor_sync(0xffffffffu, mx, m));
    float e = expf(logit - mx);
    float se = e;
#pragma unroll
    for (int m = 2; m <= 16; m <<= 1) se += __shfl_xor_sync(0xffffffffu, se, m);
    float aw = e / se;

    const float* rp = refp + ((size_t)r * 4 + l) * 2;
    float locx = rp[0] + offx / (float)W;
    float locy = rp[1] + offy / (float)H;
    float px = locx * (float)W - 0.5f;
    float py = locy * (float)H - 0.5f;
    float x0f = floorf(px), y0f = floorf(py);
    float fx = px - x0f, fy = py - y0f;
    int x0 = (int)x0f, y0 = (int)y0f;

    float cw00 = (1.f - fx) * (1.f - fy) * aw;
    float cw10 = fx * (1.f - fy) * aw;
    float cw01 = (1.f - fx) * fy * aw;
    float cw11 = fx * fy * aw;

    const float* base = newv + ((size_t)b * LV_ + start) * C_ + h * DH_ + half * 8;

    float acc[8] = {0.f, 0.f, 0.f, 0.f, 0.f, 0.f, 0.f, 0.f};
    auto corner = [&](int xi, int yi, float cw) {
        if ((unsigned)xi < (unsigned)W && (unsigned)yi < (unsigned)H) {
            const float4* vp = (const float4*)(base + ((size_t)yi * W + xi) * C_);
            float4 v0 = vp[0], v1 = vp[1];
            acc[0] += cw * v0.x; acc[1] += cw * v0.y;
            acc[2] += cw * v0.z; acc[3] += cw * v0.w;
            acc[4] += cw * v1.x; acc[5] += cw * v1.y;
            acc[6] += cw * v1.z; acc[7] += cw * v1.w;
        }
    };
    corner(x0,     y0,     cw00);
    corner(x0 + 1, y0,     cw10);
    corner(x0,     y0 + 1, cw01);
    corner(x0 + 1, y0 + 1, cw11);

#pragma unroll
    for (int m = 2; m <= 16; m <<= 1) {
#pragma unroll
        for (int i = 0; i < 8; i++)
            acc[i] += __shfl_xor_sync(0xffffffffu, acc[i], m);
    }

    if (s == 0) {
        float* dst = g_samp + (size_t)r * C_ + h * DH_ + half * 8;
        *(float4*)(dst + 0) = make_float4(acc[0], acc[1], acc[2], acc[3]);
        *(float4*)(dst + 4) = make_float4(acc[4], acc[5], acc[6], acc[7]);
    }
}

// ---------------- launch ----------------
extern "C" void kernel_launch(void* const* d_in, const int* in_sizes, int n_in,
                              void* d_out, int out_size)
{
    const float* query  = (const float*)d_in[0];
    const float* refp   = (const float*)d_in[1];
    const float* value  = (const float*)d_in[2];
    const float* W_off  = (const float*)d_in[5];
    const float* b_off  = (const float*)d_in[6];
    const float* W_attn = (const float*)d_in[7];
    const float* b_attn = (const float*)d_in[8];
    const float* W_val  = (const float*)d_in[9];
    const float* b_val  = (const float*)d_in[10];
    const float* W_out  = (const float*)d_in[11];
    const float* b_out  = (const float*)d_in[12];

    float* NEWQ = (float*)d_out;
    float* NEWV = NEWQ + NEWQ_SIZE_;

    float *p_offatt, *p_samp, *p_bcat;
    uint32_t *p_wb;
    cudaGetSymbolAddress((void**)&p_offatt, g_offatt);
    cudaGetSymbolAddress((void**)&p_samp,   g_samp);
    cudaGetSymbolAddress((void**)&p_bcat,   g_bcat);
    cudaGetSymbolAddress((void**)&p_wb,     g_wb);

    cudaFuncSetAttribute(hmma_gemm, cudaFuncAttributeMaxDynamicSharedMemorySize, VP_SMEM);

    // 1) prep weight images + bias concat
    prep_images<<<5, 256>>>(W_val, W_off, W_attn, W_out);
    concat_bias<<<1, NCAT_>>>(b_off, b_attn);

    // 2) value projection -> new_value (persistent: 3 CTAs/SM x 148 SMs)
    {
        int mtiles = MVAL_ / CTM;               // 13770
        hmma_gemm<<<dim3(444, 1), 128, VP_SMEM>>>(
            value, p_wb, b_val, NEWV, MVAL_, 128, mtiles);
    }

    // 3) offsets + attn logits (3 weight chunks: indices 1..3)
    {
        int mtiles = (NROWS_ + CTM - 1) / CTM;  // 517
        hmma_gemm<<<dim3(mtiles, 3), 128, VP_SMEM>>>(
            query, p_wb + 8192, p_bcat, p_offatt, NROWS_, NCAT_, mtiles);
    }

    // 4) bilinear gather + fused softmax
    gather_kernel<<<NROWS_ * NH_ / 4, 128>>>(NEWV, refp);

    // 5) output projection -> new_query (chunk 4)
    {
        int mtiles = (NROWS_ + CTM - 1) / CTM;
        hmma_gemm<<<dim3(mtiles, 1), 128, VP_SMEM>>>(
            p_samp, p_wb + 4 * 8192, b_out, NEWQ, NROWS_, 128, mtiles);
    }
}

// round 13
// speedup vs baseline: 1.6276x; 1.6276x over previous
#include <cuda_runtime.h>
#include <cuda_fp16.h>
#include <math.h>
#include <stdint.h>

// ---------------- problem constants (fixed by dataset) ----------------
#define B_     8
#define T2_    27
#define T3_    9
#define P_     17
#define C_     128
#define BT2_   216
#define LQ_    153
#define LV_    4080
#define NH_    8
#define NL_    4
#define NP_    4
#define DH_    16
#define NROWS_ (BT2_*LQ_)     // 33048
#define MVAL_  (BT2_*LV_)     // 881280
#define NEWQ_SIZE_ ((size_t)NROWS_*C_)
#define NOFF_  256
#define NCAT_  384

// ---------------- scratch ----------------
__device__ float g_offatt[(size_t)NROWS_ * NCAT_];
__device__ float g_samp[(size_t)NROWS_ * C_];
__device__ float g_bcat[NCAT_];
// fp16 weight images, XOR-swizzled [n][k] layout with K-PERMUTED columns,
// 5 chunks of 128x128:
// 0: W_val, 1: W_off[0:128), 2: W_off[128:256), 3: W_attn, 4: W_out
__device__ uint32_t g_wb[5 * 8192];   // 32KB per chunk

__device__ __forceinline__ uint32_t smem_u32(const void* p) {
    uint32_t a;
    asm("{ .reg .u64 t; cvta.to.shared.u64 t, %1; cvt.u32.u64 %0, t; }" : "=r"(a) : "l"(p));
    return a;
}

// swizzled byte offset within a 256B row: c = byte col (0..255), rm = row & 7
__device__ __forceinline__ uint32_t swz(uint32_t c, uint32_t rm) {
    return (c & 15u) | ((((c >> 4) ^ rm) & 15u) << 4);
}

// ---------------- prep: build 5 fp16 K-permuted weight-chunk images --------
// Fragment slot l (within a 16-col k-block, l = 8h + 2j + b) is fed by A's
// physical column p = 4j + 2h + b (so A fragments load as one float4).
// The W image must hold W[n][p(l)] at slot l for the contraction to match.
__global__ void prep_images(const float* __restrict__ W_val,
                            const float* __restrict__ W_off,
                            const float* __restrict__ W_attn,
                            const float* __restrict__ W_out)
{
    const float* srcs[5] = {W_val, W_off, W_off + 16384, W_attn, W_out};
    const float* W = srcs[blockIdx.x];
    unsigned short* img = (unsigned short*)(g_wb + blockIdx.x * 8192);
    for (int i = threadIdx.x; i < 16384; i += 256) {
        int n = i >> 7, l = i & 127;
        int lo = l & 15;
        int h = lo >> 3, j = (lo >> 1) & 3, b = lo & 1;
        int srck = (l & ~15) + 4 * j + 2 * h + b;
        __half hv = __float2half_rn(W[n * 128 + srck]);
        uint32_t byte = (uint32_t)n * 256u + swz((uint32_t)l * 2u, (uint32_t)(n & 7));
        img[byte >> 1] = *(unsigned short*)&hv;
    }
}

__global__ void concat_bias(const float* __restrict__ boff, const float* __restrict__ battn) {
    int i = threadIdx.x;
    if (i < NCAT_) g_bcat[i] = (i < NOFF_) ? boff[i] : battn[i - NOFF_];
}

// ---------------- ldmatrix / mma helpers ----------------
#define LDSM4(r0, r1, r2, r3, addr) \
    asm volatile("ldmatrix.sync.aligned.m8n8.x4.shared.b16 {%0,%1,%2,%3}, [%4];" \
                 : "=r"(r0), "=r"(r1), "=r"(r2), "=r"(r3) : "r"(addr))

#define MMAH16816(c, a, b0, b1) \
    asm volatile("mma.sync.aligned.m16n8k16.row.col.f32.f16.f16.f32 " \
                 "{%0,%1,%2,%3},{%4,%5,%6,%7},{%8,%9},{%0,%1,%2,%3};" \
                 : "+f"((c)[0]), "+f"((c)[1]), "+f"((c)[2]), "+f"((c)[3]) \
                 : "r"((a)[0]), "r"((a)[1]), "r"((a)[2]), "r"((a)[3]), "r"(b0), "r"(b1))

// ---------------- unified HMMA fp16 GEMM (K-permuted fragments) ------------
// Out = A * W^T + bias.  Both operands fp16 (rel err ~4.3e-4 total).
// CTA: 128 threads (4 warps), tile 64(M) x 128(N), K = 128, warp 32x64.
// A fragments: one LDG.128 per (band, row-half, k-step) thanks to the
// K-permutation baked into the W image. No A smem. Barrier-free mainloop.
#define CTM 64
#define VP_SMEM 32768

__global__ __launch_bounds__(128, 4)
void hmma_gemm(const float* __restrict__ A,
               const uint32_t* __restrict__ wimg_base,
               const float* __restrict__ bias_base,
               float* __restrict__ Out,
               int M, int ldout, int mtiles)
{
    extern __shared__ char sm[];
    const uint32_t sbase = smem_u32(sm);
    const int tid = threadIdx.x;
    const int wid = tid >> 5;
    const int lane = tid & 31;
    const int wm = wid & 1;          // m half (32 rows)
    const int wn = wid >> 1;         // n half (64 cols)
    const int colbase = blockIdx.y * 128;
    const float* bias = bias_base + colbase;

    // copy this chunk's pre-permuted fp16 W image into smem (once)
    {
        const float4* s4 = (const float4*)(wimg_base + blockIdx.y * 8192);
        float4* d4 = (float4*)sm;
#pragma unroll
        for (int i = 0; i < 16; i++) d4[tid + i * 128] = s4[tid + i * 128];
    }
    __syncthreads();   // only barrier in the kernel

    // B fragment addressing (loop-invariant)
    const int sel = lane >> 3;            // 0..3
    const int li  = lane & 7;
    const int bchunkbit = sel & 1;
    const int bro = (sel >> 1) * 8 + li;
    uint32_t bBase[4];
#pragma unroll
    for (int g = 0; g < 4; g++) {
        uint32_t nrow = (uint32_t)(wn * 64 + g * 16 + bro);
        bBase[g] = sbase + nrow * 256u;
    }

    // A fragment addressing: row = lane>>2, float4 col group = lane&3
    const int ar = lane >> 2;             // 0..7
    const int aj = lane & 3;              // float4 group

    for (int tile = blockIdx.x; tile < mtiles; tile += gridDim.x) {
        const int bm = tile * CTM;
        const int r0 = bm + wm * 32 + ar;

        float c[2][8][4];
#pragma unroll
        for (int s = 0; s < 2; s++)
#pragma unroll
            for (int t = 0; t < 8; t++)
#pragma unroll
                for (int j = 0; j < 4; j++) c[s][t][j] = 0.f;

#pragma unroll
        for (int kk = 0; kk < 8; kk++) {
            // A: one float4 per (band, row-half); permutation puts fragment
            // slots {2j,2j+1} in .xy and {8+2j,8+2j+1} in .zw
            uint32_t a[2][4];
#pragma unroll
            for (int s = 0; s < 2; s++) {
                const int r = r0 + s * 16;
                const bool v0 = r < M;
                const bool v1 = (r + 8) < M;
                const float* p0 = A + (size_t)r * 128 + kk * 16 + aj * 4;
                float4 f0 = v0 ? *(const float4*)(p0)          : make_float4(0.f, 0.f, 0.f, 0.f);
                float4 f1 = v1 ? *(const float4*)(p0 + 8 * 128): make_float4(0.f, 0.f, 0.f, 0.f);
                __half2 q;
                q = __floats2half2_rn(f0.x, f0.y); a[s][0] = *(uint32_t*)&q;
                q = __floats2half2_rn(f1.x, f1.y); a[s][1] = *(uint32_t*)&q;
                q = __floats2half2_rn(f0.z, f0.w); a[s][2] = *(uint32_t*)&q;
                q = __floats2half2_rn(f1.z, f1.w); a[s][3] = *(uint32_t*)&q;
            }

            const uint32_t offB = (uint32_t)(((kk * 2 + bchunkbit) ^ li) << 4);
#pragma unroll
            for (int g = 0; g < 4; g++) {
                uint32_t bh[4];
                LDSM4(bh[0], bh[1], bh[2], bh[3], bBase[g] + offB);
#pragma unroll
                for (int s = 0; s < 2; s++) {
                    MMAH16816(c[s][2 * g],     a[s], bh[0], bh[1]);
                    MMAH16816(c[s][2 * g + 1], a[s], bh[2], bh[3]);
                }
            }
        }

        // epilogue: bias + direct global stores
        {
            const int ncol = wn * 64 + 2 * (lane & 3);
#pragma unroll
            for (int s = 0; s < 2; s++) {
                const int m0 = bm + wm * 32 + s * 16 + (lane >> 2);
                const bool v0 = m0 < M;
                const bool v1 = (m0 + 8) < M;
                float* o0 = Out + (size_t)m0 * ldout + colbase;
                float* o1 = Out + (size_t)(m0 + 8) * ldout + colbase;
#pragma unroll
                for (int t = 0; t < 8; t++) {
                    int n = ncol + t * 8;
                    float2 bb = __ldg((const float2*)(bias + n));
                    if (v0) *(float2*)(o0 + n) = make_float2(c[s][t][0] + bb.x, c[s][t][1] + bb.y);
                    if (v1) *(float2*)(o1 + n) = make_float2(c[s][t][2] + bb.x, c[s][t][3] + bb.y);
                }
            }
        }
    }
}

// ---------------- deformable bilinear gather (softmax fused) ----------------
__global__ __launch_bounds__(128) void gather_kernel(
    const float* __restrict__ newv,
    const float* __restrict__ refp)
{
    int g = blockIdx.x * 4 + (threadIdx.x >> 5);
    int r = g >> 3;
    int h = g & 7;
    int lane = threadIdx.x & 31;
    int s = lane >> 1;           // sample 0..15
    int half = lane & 1;
    int l = s >> 2, p = s & 3;
    int b = r / LQ_;

    const int W = 48 >> l;
    const int H = 64 >> l;
    const int start = 4096 - (4096 >> (2 * l));

    int sidx = (h * 4 + l) * 4 + p;
    const float* orow = g_offatt + (size_t)r * NCAT_;
    float offx = orow[sidx * 2 + 0];
    float offy = orow[sidx * 2 + 1];

    // fused softmax over the 16 samples of this (r,h)
    float logit = orow[NOFF_ + h * 16 + s];
    float mx = logit;
#pragma unroll
    for (int m = 2; m <= 16; m <<= 1) mx = fmaxf(mx, __shfl_xor_sync(0xffffffffu, mx, m));
    float e = expf(logit - mx);
    float se = e;
#pragma unroll
    for (int m = 2; m <= 16; m <<= 1) se += __shfl_xor_sync(0xffffffffu, se, m);
    float aw = e / se;

    const float* rp = refp + ((size_t)r * 4 + l) * 2;
    float locx = rp[0] + offx / (float)W;
    float locy = rp[1] + offy / (float)H;
    float px = locx * (float)W - 0.5f;
    float py = locy * (float)H - 0.5f;
    float x0f = floorf(px), y0f = floorf(py);
    float fx = px - x0f, fy = py - y0f;
    int x0 = (int)x0f, y0 = (int)y0f;

    float cw00 = (1.f - fx) * (1.f - fy) * aw;
    float cw10 = fx * (1.f - fy) * aw;
    float cw01 = (1.f - fx) * fy * aw;
    float cw11 = fx * fy * aw;

    const float* base = newv + ((size_t)b * LV_ + start) * C_ + h * DH_ + half * 8;

    float acc[8] = {0.f, 0.f, 0.f, 0.f, 0.f, 0.f, 0.f, 0.f};
    auto corner = [&](int xi, int yi, float cw) {
        if ((unsigned)xi < (unsigned)W && (unsigned)yi < (unsigned)H) {
            const float4* vp = (const float4*)(base + ((size_t)yi * W + xi) * C_);
            float4 v0 = vp[0], v1 = vp[1];
            acc[0] += cw * v0.x; acc[1] += cw * v0.y;
            acc[2] += cw * v0.z; acc[3] += cw * v0.w;
            acc[4] += cw * v1.x; acc[5] += cw * v1.y;
            acc[6] += cw * v1.z; acc[7] += cw * v1.w;
        }
    };
    corner(x0,     y0,     cw00);
    corner(x0 + 1, y0,     cw10);
    corner(x0,     y0 + 1, cw01);
    corner(x0 + 1, y0 + 1, cw11);

#pragma unroll
    for (int m = 2; m <= 16; m <<= 1) {
#pragma unroll
        for (int i = 0; i < 8; i++)
            acc[i] += __shfl_xor_sync(0xffffffffu, acc[i], m);
    }

    if (s == 0) {
        float* dst = g_samp + (size_t)r * C_ + h * DH_ + half * 8;
        *(float4*)(dst + 0) = make_float4(acc[0], acc[1], acc[2], acc[3]);
        *(float4*)(dst + 4) = make_float4(acc[4], acc[5], acc[6], acc[7]);
    }
}

// ---------------- launch ----------------
extern "C" void kernel_launch(void* const* d_in, const int* in_sizes, int n_in,
                              void* d_out, int out_size)
{
    const float* query  = (const float*)d_in[0];
    const float* refp   = (const float*)d_in[1];
    const float* value  = (const float*)d_in[2];
    const float* W_off  = (const float*)d_in[5];
    const float* b_off  = (const float*)d_in[6];
    const float* W_attn = (const float*)d_in[7];
    const float* b_attn = (const float*)d_in[8];
    const float* W_val  = (const float*)d_in[9];
    const float* b_val  = (const float*)d_in[10];
    const float* W_out  = (const float*)d_in[11];
    const float* b_out  = (const float*)d_in[12];

    float* NEWQ = (float*)d_out;
    float* NEWV = NEWQ + NEWQ_SIZE_;

    float *p_offatt, *p_samp, *p_bcat;
    uint32_t *p_wb;
    cudaGetSymbolAddress((void**)&p_offatt, g_offatt);
    cudaGetSymbolAddress((void**)&p_samp,   g_samp);
    cudaGetSymbolAddress((void**)&p_bcat,   g_bcat);
    cudaGetSymbolAddress((void**)&p_wb,     g_wb);

    cudaFuncSetAttribute(hmma_gemm, cudaFuncAttributeMaxDynamicSharedMemorySize, VP_SMEM);

    // 1) prep K-permuted weight images + bias concat
    prep_images<<<5, 256>>>(W_val, W_off, W_attn, W_out);
    concat_bias<<<1, NCAT_>>>(b_off, b_attn);

    // 2) value projection -> new_value (persistent: 4 CTAs/SM x 148 SMs)
    {
        int mtiles = MVAL_ / CTM;               // 13770
        hmma_gemm<<<dim3(592, 1), 128, VP_SMEM>>>(
            value, p_wb, b_val, NEWV, MVAL_, 128, mtiles);
    }

    // 3) offsets + attn logits (3 weight chunks: indices 1..3)
    {
        int mtiles = (NROWS_ + CTM - 1) / CTM;  // 517
        hmma_gemm<<<dim3(mtiles, 3), 128, VP_SMEM>>>(
            query, p_wb + 8192, p_bcat, p_offatt, NROWS_, NCAT_, mtiles);
    }

    // 4) bilinear gather + fused softmax
    gather_kernel<<<NROWS_ * NH_ / 4, 128>>>(NEWV, refp);

    // 5) output projection -> new_query (chunk 4)
    {
        int mtiles = (NROWS_ + CTM - 1) / CTM;
        hmma_gemm<<<dim3(mtiles, 1), 128, VP_SMEM>>>(
            p_samp, p_wb + 4 * 8192, b_out, NEWQ, NROWS_, 128, mtiles);
    }
}